// round 4
// baseline (speedup 1.0000x reference)
#include <cuda_runtime.h>
#include <math.h>
#include <stdint.h>

// Problem dimensions (fixed by the reference)
#define QD 8
#define VD 6890
#define KK 16          // neighbors per query
#define ED 256         // embedding
#define HD 8           // heads
#define DD 32          // head dim
#define NTOK (QD*VD)   // 55120 tokens
#define FF  (4*ED)     // 1024

// ---------------------------------------------------------------------------
// Scratch (device globals; no runtime allocation allowed)
// ---------------------------------------------------------------------------
__device__ float g_qh[(size_t)NTOK * ED];   // Q projection
__device__ float g_kh[(size_t)NTOK * ED];   // K projection (per source token!)
__device__ float g_vh[(size_t)NTOK * ED];   // V projection (per source token!)
__device__ float g_o [(size_t)NTOK * ED];   // attention output
__device__ float g_x1[(size_t)NTOK * ED];   // post-LN1 activations
__device__ float g_h [(size_t)NTOK * FF];   // MLP hidden
__device__ int   g_flags[2];                // [0] idx-is-int64, [1] mask-is-byte

// ---------------------------------------------------------------------------
// Dtype detection: int32 vs int64 indices, byte vs int32 mask.
// Deterministic (pure function of inputs), graph-capturable.
// ---------------------------------------------------------------------------
__global__ void detect_kernel(const void* __restrict__ bidx,
                              const void* __restrict__ graph,
                              const void* __restrict__ mask, int nElem)
{
    __shared__ int bad64, byteMask;
    if (threadIdx.x == 0) { bad64 = 0; byteMask = 0; }
    __syncthreads();

    // Interpret indices as int64. Reading n64 elements touches n64*8 bytes,
    // which is within bounds under either dtype as long as n64 <= nElem/2.
    const long long* b64 = (const long long*)bidx;
    const long long* g64 = (const long long*)graph;
    int n64 = min(nElem / 2, 2048);
    for (int i = threadIdx.x; i < n64; i += blockDim.x) {
        long long b = b64[i], g = g64[i];
        if (b < 0 || b >= QD || g < 0 || g >= VD) bad64 = 1;
    }

    // Mask bytes: int32 {0,1} values have zero bytes at offsets %4 != 0.
    const unsigned char* mb = (const unsigned char*)mask;
    int nb = min(nElem, 4096);                 // safe under either dtype
    for (int i = threadIdx.x; i < nb; i += blockDim.x)
        if ((i & 3) != 0 && mb[i] != 0) byteMask = 1;

    __syncthreads();
    if (threadIdx.x == 0) {
        g_flags[0] = bad64 ? 0 : 1;            // valid int64 view => int64 data
        g_flags[1] = byteMask;                 // nonzero odd byte => bool/uint8
    }
}

// ---------------------------------------------------------------------------
// GEMM: C[M,Ncols] = A[M,Kd] @ W[Ncols,Kd]^T + bias, with fused epilogue.
// 128x128 block, BK=8, 256 threads, 8x8 microtile (split 4+4 register layout).
// ---------------------------------------------------------------------------
#define EPI_NONE 0
#define EPI_GELU 1
#define EPI_ADD  2

template<int EPI>
__global__ void __launch_bounds__(256, 2)
gemm_kernel(const float* __restrict__ A, const float* __restrict__ W,
            const float* __restrict__ bias, const float* __restrict__ res,
            float* __restrict__ C, int M, int Ncols, int Kd)
{
    constexpr int BM = 128, BN = 128, BK = 8;
    __shared__ float As[BK][BM];
    __shared__ float Bs[BK][BN];

    const int tid  = threadIdx.x;
    const int tx   = tid & 15;          // 0..15 -> column group
    const int ty   = tid >> 4;          // 0..15 -> row group
    const int row0 = blockIdx.y * BM;
    const int col0 = blockIdx.x * BN;

    // loader mapping: one float4 per thread per tile
    const int lrow = tid >> 1;          // 0..127
    const int lcol = (tid & 1) * 4;     // 0 or 4

    float acc[8][8];
    #pragma unroll
    for (int i = 0; i < 8; i++)
        #pragma unroll
        for (int j = 0; j < 8; j++) acc[i][j] = 0.f;

    for (int kt = 0; kt < Kd; kt += BK) {
        {
            int grow = row0 + lrow;
            float4 a = make_float4(0.f, 0.f, 0.f, 0.f);
            if (grow < M)
                a = *reinterpret_cast<const float4*>(&A[(size_t)grow * Kd + kt + lcol]);
            As[lcol + 0][lrow] = a.x; As[lcol + 1][lrow] = a.y;
            As[lcol + 2][lrow] = a.z; As[lcol + 3][lrow] = a.w;

            int wrow = col0 + lrow;   // Ncols is a multiple of 128: always in range
            float4 b = *reinterpret_cast<const float4*>(&W[(size_t)wrow * Kd + kt + lcol]);
            Bs[lcol + 0][lrow] = b.x; Bs[lcol + 1][lrow] = b.y;
            Bs[lcol + 2][lrow] = b.z; Bs[lcol + 3][lrow] = b.w;
        }
        __syncthreads();

        #pragma unroll
        for (int k = 0; k < BK; k++) {
            float af[8], bf[8];
            #pragma unroll
            for (int i = 0; i < 4; i++) {
                af[i]     = As[k][ty * 4 + i];
                af[i + 4] = As[k][64 + ty * 4 + i];
                bf[i]     = Bs[k][tx * 4 + i];
                bf[i + 4] = Bs[k][64 + tx * 4 + i];
            }
            #pragma unroll
            for (int i = 0; i < 8; i++)
                #pragma unroll
                for (int j = 0; j < 8; j++)
                    acc[i][j] = fmaf(af[i], bf[j], acc[i][j]);
        }
        __syncthreads();
    }

    #pragma unroll
    for (int i = 0; i < 8; i++) {
        int r = row0 + ((i < 4) ? (ty * 4 + i) : (64 + ty * 4 + i - 4));
        if (r >= M) continue;
        #pragma unroll
        for (int j = 0; j < 8; j++) {
            int c = col0 + ((j < 4) ? (tx * 4 + j) : (64 + tx * 4 + j - 4));
            float v = acc[i][j] + bias[c];
            if (EPI == EPI_GELU)
                v = 0.5f * v * (1.0f + erff(v * 0.70710678118654752f));  // exact GELU
            if (EPI == EPI_ADD)
                v += res[(size_t)r * Ncols + c];
            C[(size_t)r * Ncols + c] = v;
        }
    }
}

// ---------------------------------------------------------------------------
// Attention: one block per token, one warp per head (8 warps).
// Gathers pre-projected kh/vh rows (project-then-gather optimization).
// Index/mask dtype resolved at runtime via g_flags.
// ---------------------------------------------------------------------------
__global__ void __launch_bounds__(256)
attn_kernel(const float* __restrict__ qh, const float* __restrict__ kh,
            const float* __restrict__ vh,
            const void* __restrict__ bidx, const void* __restrict__ graph,
            const void* __restrict__ mask,
            float* __restrict__ o)
{
    const int n    = blockIdx.x;
    const int h    = threadIdx.x >> 5;
    const int lane = threadIdx.x & 31;

    const int idx64   = g_flags[0];
    const int maskByt = g_flags[1];

    const float q = qh[(size_t)n * ED + h * DD + lane];

    float scores[KK];
    int   midx[KK];
    const float scale = 0.17677669529663687f;   // 1/sqrt(32)

    #pragma unroll
    for (int k = 0; k < KK; k++) {
        size_t e = (size_t)n * KK + k;
        int b, g;
        if (idx64) {
            b = (int)((const long long*)bidx)[e];
            g = (int)((const long long*)graph)[e];
        } else {
            b = ((const int*)bidx)[e];
            g = ((const int*)graph)[e];
        }
        int m = b * VD + g;
        midx[k] = m;
        float kd = kh[(size_t)m * ED + h * DD + lane];
        float s = q * kd;
        #pragma unroll
        for (int off = 16; off > 0; off >>= 1)
            s += __shfl_xor_sync(0xffffffffu, s, off);
        s *= scale;
        bool excl = maskByt ? (((const unsigned char*)mask)[e] != 0)
                            : (((const int*)mask)[e] != 0);
        if (excl) s = -INFINITY;                // mask==True => excluded
        scores[k] = s;
    }

    float mx = scores[0];  // k=0 guaranteed valid by reference setup
    #pragma unroll
    for (int k = 1; k < KK; k++) mx = fmaxf(mx, scores[k]);

    float sum = 0.f;
    #pragma unroll
    for (int k = 0; k < KK; k++) {
        scores[k] = expf(scores[k] - mx);   // exp(-inf) == 0 for masked
        sum += scores[k];
    }
    const float inv = 1.0f / sum;

    float acc = 0.f;
    #pragma unroll
    for (int k = 0; k < KK; k++)
        acc += scores[k] * vh[(size_t)midx[k] * ED + h * DD + lane];

    o[(size_t)n * ED + h * DD + lane] = acc * inv;
}

// ---------------------------------------------------------------------------
// LayerNorm (in place): one block per row, 256 threads (E=256).
// ---------------------------------------------------------------------------
__global__ void __launch_bounds__(256)
ln_kernel(float* __restrict__ x, const float* __restrict__ g,
          const float* __restrict__ b)
{
    __shared__ float sm[8];
    const int row  = blockIdx.x;
    const int tid  = threadIdx.x;
    const int lane = tid & 31;
    const int warp = tid >> 5;

    float v = x[(size_t)row * ED + tid];

    float s = v;
    #pragma unroll
    for (int off = 16; off > 0; off >>= 1) s += __shfl_xor_sync(0xffffffffu, s, off);
    if (lane == 0) sm[warp] = s;
    __syncthreads();
    float tot = 0.f;
    #pragma unroll
    for (int i = 0; i < 8; i++) tot += sm[i];
    const float mean = tot * (1.0f / ED);
    const float d = v - mean;
    __syncthreads();

    float s2 = d * d;
    #pragma unroll
    for (int off = 16; off > 0; off >>= 1) s2 += __shfl_xor_sync(0xffffffffu, s2, off);
    if (lane == 0) sm[warp] = s2;
    __syncthreads();
    float tot2 = 0.f;
    #pragma unroll
    for (int i = 0; i < 8; i++) tot2 += sm[i];
    const float var = tot2 * (1.0f / ED);

    x[(size_t)row * ED + tid] = d / sqrtf(var + 1e-5f) * g[tid] + b[tid];
}

// ---------------------------------------------------------------------------
// Launch
// ---------------------------------------------------------------------------
extern "C" void kernel_launch(void* const* d_in, const int* in_sizes, int n_in,
                              void* d_out, int out_size)
{
    const float* x    = (const float*)d_in[0];   // mesh_queries [Q,V,E]
    const float* Wq   = (const float*)d_in[1];
    const float* bq   = (const float*)d_in[2];
    const float* Wk   = (const float*)d_in[3];
    const float* bk   = (const float*)d_in[4];
    const float* Wv   = (const float*)d_in[5];
    const float* bv   = (const float*)d_in[6];
    const float* Wo   = (const float*)d_in[7];
    const float* bo   = (const float*)d_in[8];
    const float* ln1g = (const float*)d_in[9];
    const float* ln1b = (const float*)d_in[10];
    const float* W1   = (const float*)d_in[11];  // [1024, 256]
    const float* b1   = (const float*)d_in[12];
    const float* W2   = (const float*)d_in[13];  // [256, 1024]
    const float* b2   = (const float*)d_in[14];
    const float* ln2g = (const float*)d_in[15];
    const float* ln2b = (const float*)d_in[16];
    const void*  bidx  = d_in[17];
    const void*  graph = d_in[18];
    const void*  mask  = d_in[19];
    float* out = (float*)d_out;

    float *qh, *kh, *vh, *o, *x1, *hbuf;
    cudaGetSymbolAddress((void**)&qh,   g_qh);
    cudaGetSymbolAddress((void**)&kh,   g_kh);
    cudaGetSymbolAddress((void**)&vh,   g_vh);
    cudaGetSymbolAddress((void**)&o,    g_o);
    cudaGetSymbolAddress((void**)&x1,   g_x1);
    cudaGetSymbolAddress((void**)&hbuf, g_h);

    const dim3 blk(256);
    const int  rb = (NTOK + 127) / 128;          // 431 row blocks
    const dim3 gE (ED  / 128, rb);               // (2, 431) for 256 output cols
    const dim3 gFF(FF  / 128, rb);               // (8, 431) for 1024 output cols

    // Resolve index/mask dtypes once (deterministic, capturable)
    detect_kernel<<<1, 256>>>(bidx, graph, mask, NTOK * KK);

    // Q/K/V projections (project ONCE per token; gather projected rows later)
    gemm_kernel<EPI_NONE><<<gE, blk>>>(x, Wq, bq, nullptr, qh, NTOK, ED, ED);
    gemm_kernel<EPI_NONE><<<gE, blk>>>(x, Wk, bk, nullptr, kh, NTOK, ED, ED);
    gemm_kernel<EPI_NONE><<<gE, blk>>>(x, Wv, bv, nullptr, vh, NTOK, ED, ED);

    // Gathered neighbor attention
    attn_kernel<<<NTOK, blk>>>(qh, kh, vh, bidx, graph, mask, o);

    // Output projection + residual, then LN1 (in place)
    gemm_kernel<EPI_ADD><<<gE, blk>>>(o, Wo, bo, x, x1, NTOK, ED, ED);
    ln_kernel<<<NTOK, blk>>>(x1, ln1g, ln1b);

    // MLP: gelu(x1 @ W1^T + b1) @ W2^T + b2 + x1, then LN2 (in place on d_out)
    gemm_kernel<EPI_GELU><<<gFF, blk>>>(x1, W1, b1, nullptr, hbuf, NTOK, FF, ED);
    gemm_kernel<EPI_ADD ><<<gE,  blk>>>(hbuf, W2, b2, x1, out, NTOK, ED, FF);
    ln_kernel<<<NTOK, blk>>>(out, ln2g, ln2b);
}

// round 7
// speedup vs baseline: 1.4680x; 1.4680x over previous
#include <cuda_runtime.h>
#include <cuda_bf16.h>
#include <math.h>
#include <stdint.h>

// Problem dimensions (fixed by the reference)
#define QD 8
#define VD 6890
#define KK 16          // neighbors per query
#define ED 256         // embedding
#define HD 8           // heads
#define DD 32          // head dim
#define NTOK (QD*VD)   // 55120 tokens
#define FF  (4*ED)     // 1024

// ---------------------------------------------------------------------------
// Scratch (device globals; no runtime allocation allowed)
// ---------------------------------------------------------------------------
__device__ float g_qh[(size_t)NTOK * ED];
__device__ float g_kh[(size_t)NTOK * ED];
__device__ float g_vh[(size_t)NTOK * ED];
__device__ float g_o [(size_t)NTOK * ED];
__device__ float g_x1[(size_t)NTOK * ED];
__device__ float g_h [(size_t)NTOK * FF];
__device__ int   g_flags[2];               // [0] idx-is-int64, [1] mask-is-byte

// ---------------------------------------------------------------------------
// Helpers
// ---------------------------------------------------------------------------
__device__ __forceinline__ uint32_t smem_u32(const void* p) {
    uint32_t a;
    asm("{ .reg .u64 t; cvta.to.shared.u64 t, %1; cvt.u32.u64 %0, t; }" : "=r"(a) : "l"(p));
    return a;
}
__device__ __forceinline__ unsigned pack_bf2(float a, float b) {
    __nv_bfloat162 t = __floats2bfloat162_rn(a, b);   // x = a (low), y = b (high)
    return *reinterpret_cast<unsigned*>(&t);
}
__device__ __forceinline__ void ldm_x4(uint32_t addr, uint32_t& r0, uint32_t& r1,
                                       uint32_t& r2, uint32_t& r3) {
    asm volatile("ldmatrix.sync.aligned.m8n8.x4.shared.b16 {%0,%1,%2,%3}, [%4];"
                 : "=r"(r0), "=r"(r1), "=r"(r2), "=r"(r3) : "r"(addr));
}
__device__ __forceinline__ void mma_bf16(float* c, const uint32_t* a, uint32_t b0, uint32_t b1) {
    asm volatile("mma.sync.aligned.m16n8k16.row.col.f32.bf16.bf16.f32 "
                 "{%0,%1,%2,%3}, {%4,%5,%6,%7}, {%8,%9}, {%0,%1,%2,%3};"
                 : "+f"(c[0]), "+f"(c[1]), "+f"(c[2]), "+f"(c[3])
                 : "r"(a[0]), "r"(a[1]), "r"(a[2]), "r"(a[3]), "r"(b0), "r"(b1));
}

// ---------------------------------------------------------------------------
// Dtype detection (proven round 4)
// ---------------------------------------------------------------------------
__global__ void detect_kernel(const void* __restrict__ bidx,
                              const void* __restrict__ graph,
                              const void* __restrict__ mask, int nElem)
{
    __shared__ int bad64, byteMask;
    if (threadIdx.x == 0) { bad64 = 0; byteMask = 0; }
    __syncthreads();
    const long long* b64 = (const long long*)bidx;
    const long long* g64 = (const long long*)graph;
    int n64 = min(nElem / 2, 2048);
    for (int i = threadIdx.x; i < n64; i += blockDim.x) {
        long long b = b64[i], g = g64[i];
        if (b < 0 || b >= QD || g < 0 || g >= VD) bad64 = 1;
    }
    const unsigned char* mb = (const unsigned char*)mask;
    int nb = min(nElem, 4096);
    for (int i = threadIdx.x; i < nb; i += blockDim.x)
        if ((i & 3) != 0 && mb[i] != 0) byteMask = 1;
    __syncthreads();
    if (threadIdx.x == 0) { g_flags[0] = bad64 ? 0 : 1; g_flags[1] = byteMask; }
}

// ---------------------------------------------------------------------------
// bf16-split mma.sync GEMM: C[M,N] = A[M,Kd] @ W[N,Kd]^T + bias (+epilogue).
// 256 thr, BM=BN=128, BK=32, double-buffered smem (A/B hi/lo bf16 tiles).
// Split: v = hi + lo (both bf16); 3 MMAs: hi*hi + hi*lo + lo*hi.
// ---------------------------------------------------------------------------
#define EPI_NONE 0
#define EPI_GELU 1
#define EPI_ADD  2

// Per-stage tile layout (bf16, 64-byte rows, chunk-XOR swizzle):
//   A_hi @0, A_lo @8K, B_hi @16K, B_lo @24K; stage stride 32K; total 64K.
#define TILE_BYTES  8192
#define STAGE_BYTES 32768
#define GSMEM_BYTES 65536

// swizzled byte offset within a tile: rows of 64B, 16B chunks XOR'ed by row%4
__device__ __forceinline__ uint32_t swz_addr(int row, int kchunk8) {
    return (uint32_t)(row * 64 + (((kchunk8) ^ (row & 3)) << 4));
}

template<int EPI>
__global__ void __launch_bounds__(256, 1)
mma_gemm(const float* __restrict__ A, const float* __restrict__ W,
         const float* __restrict__ bias, const float* __restrict__ res,
         float* __restrict__ C, int M, int Ncols, int Kd)
{
    extern __shared__ char smem[];
    const uint32_t sb = smem_u32(smem);

    const int tid  = threadIdx.x;
    const int wid  = tid >> 5;
    const int lane = tid & 31;
    const int wm   = wid & 1;            // 2 warps over M
    const int wn   = wid >> 1;           // 4 warps over N
    const int row0 = blockIdx.y * 128;
    const int col0 = blockIdx.x * 128;

    float acc[4][4][4];
    #pragma unroll
    for (int i = 0; i < 4; i++)
        #pragma unroll
        for (int j = 0; j < 4; j++)
            #pragma unroll
            for (int q = 0; q < 4; q++) acc[i][j][q] = 0.f;

    const int nChunks = Kd >> 5;
    float4 ra[4], rb[4];

    // ---- LDG of one chunk into regs
    auto LDG = [&](int c) {
        #pragma unroll
        for (int i = 0; i < 4; i++) {
            int slot = tid + i * 256;
            int row = slot >> 3, c4 = slot & 7;
            int gr = row0 + row;
            ra[i] = (gr < M) ? *reinterpret_cast<const float4*>(&A[(size_t)gr * Kd + c * 32 + c4 * 4])
                             : make_float4(0.f, 0.f, 0.f, 0.f);
            rb[i] = *reinterpret_cast<const float4*>(&W[(size_t)(col0 + row) * Kd + c * 32 + c4 * 4]);
        }
    };
    // ---- convert + store regs into stage s
    auto STS = [&](int s) {
        char* st = smem + s * STAGE_BYTES;
        #pragma unroll
        for (int i = 0; i < 4; i++) {
            int slot = tid + i * 256;
            int row = slot >> 3, c4 = slot & 7;
            uint32_t byte = (uint32_t)(row * 64 + (((c4 >> 1) ^ (row & 3)) << 4) + (c4 & 1) * 8);
            {
                float4 v = ra[i];
                __nv_bfloat16 hx = __float2bfloat16(v.x), hy = __float2bfloat16(v.y);
                __nv_bfloat16 hz = __float2bfloat16(v.z), hw = __float2bfloat16(v.w);
                uint2 hi = make_uint2(pack_bf2(__bfloat162float(hx), __bfloat162float(hy)),
                                      pack_bf2(__bfloat162float(hz), __bfloat162float(hw)));
                uint2 lo = make_uint2(pack_bf2(v.x - __bfloat162float(hx), v.y - __bfloat162float(hy)),
                                      pack_bf2(v.z - __bfloat162float(hz), v.w - __bfloat162float(hw)));
                *reinterpret_cast<uint2*>(st + 0 * TILE_BYTES + byte) = hi;
                *reinterpret_cast<uint2*>(st + 1 * TILE_BYTES + byte) = lo;
            }
            {
                float4 v = rb[i];
                __nv_bfloat16 hx = __float2bfloat16(v.x), hy = __float2bfloat16(v.y);
                __nv_bfloat16 hz = __float2bfloat16(v.z), hw = __float2bfloat16(v.w);
                uint2 hi = make_uint2(pack_bf2(__bfloat162float(hx), __bfloat162float(hy)),
                                      pack_bf2(__bfloat162float(hz), __bfloat162float(hw)));
                uint2 lo = make_uint2(pack_bf2(v.x - __bfloat162float(hx), v.y - __bfloat162float(hy)),
                                      pack_bf2(v.z - __bfloat162float(hz), v.w - __bfloat162float(hw)));
                *reinterpret_cast<uint2*>(st + 2 * TILE_BYTES + byte) = hi;
                *reinterpret_cast<uint2*>(st + 3 * TILE_BYTES + byte) = lo;
            }
        }
    };
    // ---- compute one stage (BK=32 = two k16 steps)
    auto COMPUTE = [&](int s) {
        const uint32_t stb = sb + s * STAGE_BYTES;
        const int sub = lane >> 3, r = lane & 7;
        #pragma unroll
        for (int ks = 0; ks < 2; ks++) {
            uint32_t ahi[4][4], alo[4][4];
            #pragma unroll
            for (int mt = 0; mt < 4; mt++) {
                int arow = wm * 64 + mt * 16 + ((sub & 1) << 3) + r;
                int akc  = ks * 2 + (sub >> 1);
                uint32_t byte = swz_addr(arow, akc);
                ldm_x4(stb + 0 * TILE_BYTES + byte, ahi[mt][0], ahi[mt][1], ahi[mt][2], ahi[mt][3]);
                ldm_x4(stb + 1 * TILE_BYTES + byte, alo[mt][0], alo[mt][1], alo[mt][2], alo[mt][3]);
            }
            uint32_t bhi[4][2], blo[4][2];
            #pragma unroll
            for (int np = 0; np < 2; np++) {
                int brow = wn * 32 + np * 16 + ((sub >> 1) << 3) + r;
                int bkc  = ks * 2 + (sub & 1);
                uint32_t byte = swz_addr(brow, bkc);
                uint32_t q0, q1, q2, q3;
                ldm_x4(stb + 2 * TILE_BYTES + byte, q0, q1, q2, q3);
                bhi[np * 2][0] = q0; bhi[np * 2][1] = q1;
                bhi[np * 2 + 1][0] = q2; bhi[np * 2 + 1][1] = q3;
                ldm_x4(stb + 3 * TILE_BYTES + byte, q0, q1, q2, q3);
                blo[np * 2][0] = q0; blo[np * 2][1] = q1;
                blo[np * 2 + 1][0] = q2; blo[np * 2 + 1][1] = q3;
            }
            #pragma unroll
            for (int mt = 0; mt < 4; mt++)
                #pragma unroll
                for (int nt = 0; nt < 4; nt++) {
                    mma_bf16(acc[mt][nt], ahi[mt], bhi[nt][0], bhi[nt][1]);
                    mma_bf16(acc[mt][nt], ahi[mt], blo[nt][0], blo[nt][1]);
                    mma_bf16(acc[mt][nt], alo[mt], bhi[nt][0], bhi[nt][1]);
                }
        }
    };

    // ---- pipelined main loop
    LDG(0);
    STS(0);
    __syncthreads();
    if (nChunks > 1) LDG(1);
    for (int c = 0; c < nChunks; c++) {
        COMPUTE(c & 1);
        if (c + 1 < nChunks) {
            __syncthreads();
            STS((c + 1) & 1);
            __syncthreads();
            if (c + 2 < nChunks) LDG(c + 2);
        }
    }

    // ---- epilogue: direct stores with fused bias / gelu / residual
    #pragma unroll
    for (int mt = 0; mt < 4; mt++) {
        #pragma unroll
        for (int half = 0; half < 2; half++) {
            int gr = row0 + wm * 64 + mt * 16 + (lane >> 2) + half * 8;
            if (gr >= M) continue;
            #pragma unroll
            for (int nt = 0; nt < 4; nt++) {
                int gc = col0 + wn * 32 + nt * 8 + (lane & 3) * 2;
                float v0 = acc[mt][nt][half * 2 + 0] + bias[gc + 0];
                float v1 = acc[mt][nt][half * 2 + 1] + bias[gc + 1];
                if (EPI == EPI_GELU) {
                    v0 = 0.5f * v0 * (1.0f + erff(v0 * 0.70710678118654752f));
                    v1 = 0.5f * v1 * (1.0f + erff(v1 * 0.70710678118654752f));
                }
                if (EPI == EPI_ADD) {
                    float2 rr = *reinterpret_cast<const float2*>(&res[(size_t)gr * Ncols + gc]);
                    v0 += rr.x; v1 += rr.y;
                }
                *reinterpret_cast<float2*>(&C[(size_t)gr * Ncols + gc]) = make_float2(v0, v1);
            }
        }
    }
}

// ---------------------------------------------------------------------------
// Attention (unchanged; proven correct in round 4)
// ---------------------------------------------------------------------------
__global__ void __launch_bounds__(256)
attn_kernel(const float* __restrict__ qh, const float* __restrict__ kh,
            const float* __restrict__ vh,
            const void* __restrict__ bidx, const void* __restrict__ graph,
            const void* __restrict__ mask,
            float* __restrict__ o)
{
    const int n    = blockIdx.x;
    const int h    = threadIdx.x >> 5;
    const int lane = threadIdx.x & 31;
    const int idx64   = g_flags[0];
    const int maskByt = g_flags[1];

    const float q = qh[(size_t)n * ED + h * DD + lane];
    float scores[KK];
    int   midx[KK];
    const float scale = 0.17677669529663687f;

    #pragma unroll
    for (int k = 0; k < KK; k++) {
        size_t e = (size_t)n * KK + k;
        int b, g;
        if (idx64) {
            b = (int)((const long long*)bidx)[e];
            g = (int)((const long long*)graph)[e];
        } else {
            b = ((const int*)bidx)[e];
            g = ((const int*)graph)[e];
        }
        int m = b * VD + g;
        midx[k] = m;
        float kd = kh[(size_t)m * ED + h * DD + lane];
        float s = q * kd;
        #pragma unroll
        for (int off = 16; off > 0; off >>= 1)
            s += __shfl_xor_sync(0xffffffffu, s, off);
        s *= scale;
        bool excl = maskByt ? (((const unsigned char*)mask)[e] != 0)
                            : (((const int*)mask)[e] != 0);
        if (excl) s = -INFINITY;
        scores[k] = s;
    }

    float mx = scores[0];
    #pragma unroll
    for (int k = 1; k < KK; k++) mx = fmaxf(mx, scores[k]);
    float sum = 0.f;
    #pragma unroll
    for (int k = 0; k < KK; k++) { scores[k] = expf(scores[k] - mx); sum += scores[k]; }
    const float inv = 1.0f / sum;

    float acc = 0.f;
    #pragma unroll
    for (int k = 0; k < KK; k++)
        acc += scores[k] * vh[(size_t)midx[k] * ED + h * DD + lane];
    o[(size_t)n * ED + h * DD + lane] = acc * inv;
}

// ---------------------------------------------------------------------------
// LayerNorm (in place; unchanged)
// ---------------------------------------------------------------------------
__global__ void __launch_bounds__(256)
ln_kernel(float* __restrict__ x, const float* __restrict__ g,
          const float* __restrict__ b)
{
    __shared__ float sm[8];
    const int row  = blockIdx.x;
    const int tid  = threadIdx.x;
    const int lane = tid & 31;
    const int warp = tid >> 5;

    float v = x[(size_t)row * ED + tid];
    float s = v;
    #pragma unroll
    for (int off = 16; off > 0; off >>= 1) s += __shfl_xor_sync(0xffffffffu, s, off);
    if (lane == 0) sm[warp] = s;
    __syncthreads();
    float tot = 0.f;
    #pragma unroll
    for (int i = 0; i < 8; i++) tot += sm[i];
    const float mean = tot * (1.0f / ED);
    const float d = v - mean;
    __syncthreads();
    float s2 = d * d;
    #pragma unroll
    for (int off = 16; off > 0; off >>= 1) s2 += __shfl_xor_sync(0xffffffffu, s2, off);
    if (lane == 0) sm[warp] = s2;
    __syncthreads();
    float tot2 = 0.f;
    #pragma unroll
    for (int i = 0; i < 8; i++) tot2 += sm[i];
    const float var = tot2 * (1.0f / ED);
    x[(size_t)row * ED + tid] = d / sqrtf(var + 1e-5f) * g[tid] + b[tid];
}

// ---------------------------------------------------------------------------
// Launch
// ---------------------------------------------------------------------------
extern "C" void kernel_launch(void* const* d_in, const int* in_sizes, int n_in,
                              void* d_out, int out_size)
{
    const float* x    = (const float*)d_in[0];
    const float* Wq   = (const float*)d_in[1];
    const float* bq   = (const float*)d_in[2];
    const float* Wk   = (const float*)d_in[3];
    const float* bk   = (const float*)d_in[4];
    const float* Wv   = (const float*)d_in[5];
    const float* bv   = (const float*)d_in[6];
    const float* Wo   = (const float*)d_in[7];
    const float* bo   = (const float*)d_in[8];
    const float* ln1g = (const float*)d_in[9];
    const float* ln1b = (const float*)d_in[10];
    const float* W1   = (const float*)d_in[11];
    const float* b1   = (const float*)d_in[12];
    const float* W2   = (const float*)d_in[13];
    const float* b2   = (const float*)d_in[14];
    const float* ln2g = (const float*)d_in[15];
    const float* ln2b = (const float*)d_in[16];
    const void*  bidx  = d_in[17];
    const void*  graph = d_in[18];
    const void*  mask  = d_in[19];
    float* out = (float*)d_out;

    float *qh, *kh, *vh, *o, *x1, *hbuf;
    cudaGetSymbolAddress((void**)&qh,   g_qh);
    cudaGetSymbolAddress((void**)&kh,   g_kh);
    cudaGetSymbolAddress((void**)&vh,   g_vh);
    cudaGetSymbolAddress((void**)&o,    g_o);
    cudaGetSymbolAddress((void**)&x1,   g_x1);
    cudaGetSymbolAddress((void**)&hbuf, g_h);

    // 64 KB dynamic smem opt-in (host-side attribute set; idempotent)
    cudaFuncSetAttribute(mma_gemm<EPI_NONE>, cudaFuncAttributeMaxDynamicSharedMemorySize, GSMEM_BYTES);
    cudaFuncSetAttribute(mma_gemm<EPI_GELU>, cudaFuncAttributeMaxDynamicSharedMemorySize, GSMEM_BYTES);
    cudaFuncSetAttribute(mma_gemm<EPI_ADD >, cudaFuncAttributeMaxDynamicSharedMemorySize, GSMEM_BYTES);

    const int  rb = (NTOK + 127) / 128;          // 431 row blocks
    const dim3 gE (ED / 128, rb);                // (2, 431)
    const dim3 gFF(FF / 128, rb);                // (8, 431)
    const dim3 blk(256);

    detect_kernel<<<1, 256>>>(bidx, graph, mask, NTOK * KK);

    mma_gemm<EPI_NONE><<<gE,  blk, GSMEM_BYTES>>>(x,    Wq, bq, nullptr, qh,  NTOK, ED, ED);
    mma_gemm<EPI_NONE><<<gE,  blk, GSMEM_BYTES>>>(x,    Wk, bk, nullptr, kh,  NTOK, ED, ED);
    mma_gemm<EPI_NONE><<<gE,  blk, GSMEM_BYTES>>>(x,    Wv, bv, nullptr, vh,  NTOK, ED, ED);

    attn_kernel<<<NTOK, 256>>>(qh, kh, vh, bidx, graph, mask, o);

    mma_gemm<EPI_ADD ><<<gE,  blk, GSMEM_BYTES>>>(o,    Wo, bo, x,       x1,  NTOK, ED, ED);
    ln_kernel<<<NTOK, 256>>>(x1, ln1g, ln1b);

    mma_gemm<EPI_GELU><<<gFF, blk, GSMEM_BYTES>>>(x1,   W1, b1, nullptr, hbuf, NTOK, FF, ED);
    mma_gemm<EPI_ADD ><<<gE,  blk, GSMEM_BYTES>>>(hbuf, W2, b2, x1,      out,  NTOK, ED, FF);
    ln_kernel<<<NTOK, 256>>>(out, ln2g, ln2b);
}